// round 3
// baseline (speedup 1.0000x reference)
#include <cuda_runtime.h>

#define T_STEPS 10
#define B_SZ    32
#define CIN     3
#define COUT    64
#define SPAT    4096            // 64*64
#define N_THR   (T_STEPS * COUT)
#define DECAY   0.2f
#define INH     1.625f

// Scratch: conv results for all timesteps, layout (t,b,c,h,w).
__device__ float    g_i[T_STEPS * B_SZ * COUT * SPAT];   // 335.5 MB
__device__ unsigned g_thr_keys[N_THR];
__device__ float4   g_thrv[N_THR];                       // {thr, 0.4*thr, 8/thr, INH*thr}
__device__ float    g_thrw[N_THR];                       // INH*thr (pass-B reload)

// ---------------------------------------------------------------------------
__global__ void init_keys() {
    int i = blockIdx.x * blockDim.x + threadIdx.x;
    if (i < N_THR) g_thr_keys[i] = 0u;   // key 0 == very negative float
}

// ---------------------------------------------------------------------------
// Conv 3x3, stride 1, pad 1. Block = 32x8 pixel tile for one (t,b); loops all
// 64 output channels. Also produces per-(t,c) global max via ordered-int keys.
__global__ void __launch_bounds__(256) conv_kernel(const float* __restrict__ x,
                                                   const float* __restrict__ Wt) {
    __shared__ float    xs[CIN][10][34];
    __shared__ float    ws[COUT * 28];       // 27 weights + 1 pad per channel
    __shared__ unsigned smax[COUT];

    const int tb  = blockIdx.z;              // t*B + b
    const int t   = tb >> 5;
    const int tid = threadIdx.y * 32 + threadIdx.x;

    for (int idx = tid; idx < COUT * 27; idx += 256) {
        int co = idx / 27;
        ws[co * 28 + (idx - co * 27)] = Wt[idx];
    }
    if (tid < COUT) { ws[tid * 28 + 27] = 0.f; smax[tid] = 0u; }

    const float* xb = x + tb * (CIN * SPAT);
    const int y0 = blockIdx.y * 8;
    const int x0 = blockIdx.x * 32;
    for (int idx = tid; idx < CIN * 340; idx += 256) {
        int ci  = idx / 340;
        int rem = idx - ci * 340;
        int yy  = rem / 34;
        int xx  = rem - yy * 34;
        int gy = y0 + yy - 1, gx = x0 + xx - 1;
        float v = 0.f;
        if ((unsigned)gy < 64u && (unsigned)gx < 64u) v = xb[ci * SPAT + gy * 64 + gx];
        xs[ci][yy][xx] = v;
    }
    __syncthreads();

    const int px = threadIdx.x, py = threadIdx.y;
    float r[27];
#pragma unroll
    for (int ci = 0; ci < 3; ci++)
#pragma unroll
        for (int ky = 0; ky < 3; ky++)
#pragma unroll
            for (int kx = 0; kx < 3; kx++)
                r[ci * 9 + ky * 3 + kx] = xs[ci][py + ky][px + kx];

    float* out = g_i + tb * (COUT * SPAT) + (y0 + py) * 64 + x0 + px;

#pragma unroll 1
    for (int co = 0; co < COUT; co++) {
        float wl[28];
        float4* wlv = (float4*)wl;
        const float4* wv = (const float4*)(ws + co * 28);
#pragma unroll
        for (int q = 0; q < 7; q++) wlv[q] = wv[q];

        float a0 = 0.f, a1 = 0.f, a2 = 0.f;
#pragma unroll
        for (int j = 0; j < 9; j++) {
            a0 = fmaf(r[j],      wl[j],      a0);
            a1 = fmaf(r[j + 9],  wl[j + 9],  a1);
            a2 = fmaf(r[j + 18], wl[j + 18], a2);
        }
        float acc = (a0 + a1) + a2;
        out[co * SPAT] = acc;

        unsigned u   = __float_as_uint(acc);
        unsigned key = ((int)u < 0) ? ~u : (u | 0x80000000u);   // order-preserving
        key = __reduce_max_sync(0xffffffffu, key);
        if (threadIdx.x == 0) atomicMax(&smax[co], key);
    }
    __syncthreads();
    if (tid < COUT) atomicMax(&g_thr_keys[t * COUT + tid], smax[tid]);
}

// ---------------------------------------------------------------------------
__global__ void finalize_thr() {
    int i = blockIdx.x * blockDim.x + threadIdx.x;
    if (i < N_THR) {
        unsigned k = g_thr_keys[i];
        unsigned u = (k & 0x80000000u) ? (k & 0x7FFFFFFFu) : ~k;
        float thr  = __uint_as_float(u) + 1e-4f;
        g_thrv[i]  = make_float4(thr, 0.4f * thr, 8.0f / thr, INH * thr);
        g_thrw[i]  = INH * thr;
    }
}

// ---------------------------------------------------------------------------
// LIF + ASF + WTA + inhibition. ONE THREAD OWNS ONE PIXEL: mem[64] lives in
// registers, WTA argmax is an in-register scan. No smem, no barriers, no
// shuffles. Per timestep: 64 independent coalesced LDG (lane = pixel,
// channel-strided) -> huge MLP; 64 coalesced STG.
__global__ void __launch_bounds__(256) lif_kernel(float* __restrict__ out) {
    const int pid = blockIdx.x * 256 + threadIdx.x;   // global pixel id
    const int b   = pid >> 12;
    const int sp  = pid & 4095;

    float mem[COUT];
#pragma unroll
    for (int c = 0; c < COUT; c++) mem[c] = 0.f;

#pragma unroll 1
    for (int t = 0; t < T_STEPS; t++) {
        const float* __restrict__ ib = g_i + ((long)(t * B_SZ + b) * COUT) * SPAT + sp;
        const float4* __restrict__ tvp = g_thrv + t * COUT;

        unsigned long long mask = 0ull;
        float bestsc = -1.f;
        int   bestc  = 0;

#pragma unroll
        for (int c = 0; c < COUT; c++) {
            const float  iv = ib[c * SPAT];
            const float4 tv = __ldg(&tvp[c]);
            // ASF: thr * sigmoid((max(i,0) - 0.4*thr) * (8/thr))
            float z   = (fmaxf(iv, 0.f) - tv.y) * tv.z;
            float asf = tv.x / (1.f + expf(-z));
            float m   = fmaf(mem[c], DECAY, asf);
            mem[c] = m;
            bool  s  = m > tv.x;
            float sc = s ? m : 0.f;
            if (s) mask |= (1ull << c);
            if (sc > bestsc) { bestsc = sc; bestc = c; }   // strict > keeps first index
        }

        const float any = (float)((mask >> bestc) & 1ull); // winner's spike = any_sp
        float* __restrict__ ob = out + ((long)(t * B_SZ + b) * COUT) * SPAT + sp;
        const float* __restrict__ twp = g_thrw + t * COUT;

#pragma unroll
        for (int c = 0; c < COUT; c++) {
            const float s  = (float)((mask >> c) & 1ull);
            const float sn = (c == bestc) ? s : 0.f;
            const float w  = __ldg(&twp[c]);
            mem[c] = (sn > 0.f) ? 0.f : fmaf(-w, any, mem[c]);
            ob[c * SPAT] = sn;
        }
    }
}

// ---------------------------------------------------------------------------
extern "C" void kernel_launch(void* const* d_in, const int* in_sizes, int n_in,
                              void* d_out, int out_size) {
    const float* x = (const float*)d_in[0];
    const float* W = (const float*)d_in[1];
    if (n_in >= 2 && in_sizes[0] == COUT * CIN * 9) {  // defensive order swap
        const float* tmp = x; x = W; W = tmp;
    }

    init_keys<<<1, N_THR>>>();

    dim3 cb(32, 8);
    dim3 cg(2, 8, T_STEPS * B_SZ);
    conv_kernel<<<cg, cb>>>(x, W);

    finalize_thr<<<1, N_THR>>>();

    lif_kernel<<<(B_SZ * SPAT) / 256, 256>>>((float*)d_out);
}

// round 4
// speedup vs baseline: 3.7720x; 3.7720x over previous
#include <cuda_runtime.h>

#define T_STEPS 10
#define B_SZ    32
#define CIN     3
#define COUT    64
#define SPAT    4096            // 64*64
#define N_THR   (T_STEPS * COUT)
#define DECAY   0.2f
#define INH     1.625f

// Scratch: conv results for all timesteps, layout (t,b,c,h,w).
__device__ float    g_i[T_STEPS * B_SZ * COUT * SPAT];   // 335.5 MB
__device__ unsigned g_thr_keys[N_THR];
__device__ float4   g_thrv[N_THR];                       // {thr, 0.4*thr, 8/thr, INH*thr}

// ---------------------------------------------------------------------------
__global__ void init_keys() {
    int i = blockIdx.x * blockDim.x + threadIdx.x;
    if (i < N_THR) g_thr_keys[i] = 0u;   // key 0 == very negative float
}

// ---------------------------------------------------------------------------
// Conv 3x3, stride 1, pad 1. Block = 32x8 pixel tile for one (t,b); loops all
// 64 output channels. Also produces per-(t,c) global max via ordered-int keys.
__global__ void __launch_bounds__(256) conv_kernel(const float* __restrict__ x,
                                                   const float* __restrict__ Wt) {
    __shared__ float    xs[CIN][10][34];
    __shared__ float    ws[COUT * 28];       // 27 weights + 1 pad per channel
    __shared__ unsigned smax[COUT];

    const int tb  = blockIdx.z;              // t*B + b
    const int t   = tb >> 5;
    const int tid = threadIdx.y * 32 + threadIdx.x;

    for (int idx = tid; idx < COUT * 27; idx += 256) {
        int co = idx / 27;
        ws[co * 28 + (idx - co * 27)] = Wt[idx];
    }
    if (tid < COUT) { ws[tid * 28 + 27] = 0.f; smax[tid] = 0u; }

    const float* xb = x + tb * (CIN * SPAT);
    const int y0 = blockIdx.y * 8;
    const int x0 = blockIdx.x * 32;
    for (int idx = tid; idx < CIN * 340; idx += 256) {
        int ci  = idx / 340;
        int rem = idx - ci * 340;
        int yy  = rem / 34;
        int xx  = rem - yy * 34;
        int gy = y0 + yy - 1, gx = x0 + xx - 1;
        float v = 0.f;
        if ((unsigned)gy < 64u && (unsigned)gx < 64u) v = xb[ci * SPAT + gy * 64 + gx];
        xs[ci][yy][xx] = v;
    }
    __syncthreads();

    const int px = threadIdx.x, py = threadIdx.y;
    float r[27];
#pragma unroll
    for (int ci = 0; ci < 3; ci++)
#pragma unroll
        for (int ky = 0; ky < 3; ky++)
#pragma unroll
            for (int kx = 0; kx < 3; kx++)
                r[ci * 9 + ky * 3 + kx] = xs[ci][py + ky][px + kx];

    float* out = g_i + tb * (COUT * SPAT) + (y0 + py) * 64 + x0 + px;

#pragma unroll 1
    for (int co = 0; co < COUT; co++) {
        float wl[28];
        float4* wlv = (float4*)wl;
        const float4* wv = (const float4*)(ws + co * 28);
#pragma unroll
        for (int q = 0; q < 7; q++) wlv[q] = wv[q];

        float a0 = 0.f, a1 = 0.f, a2 = 0.f;
#pragma unroll
        for (int j = 0; j < 9; j++) {
            a0 = fmaf(r[j],      wl[j],      a0);
            a1 = fmaf(r[j + 9],  wl[j + 9],  a1);
            a2 = fmaf(r[j + 18], wl[j + 18], a2);
        }
        float acc = (a0 + a1) + a2;
        out[co * SPAT] = acc;

        unsigned u   = __float_as_uint(acc);
        unsigned key = ((int)u < 0) ? ~u : (u | 0x80000000u);   // order-preserving
        key = __reduce_max_sync(0xffffffffu, key);
        if (threadIdx.x == 0) atomicMax(&smax[co], key);
    }
    __syncthreads();
    if (tid < COUT) atomicMax(&g_thr_keys[t * COUT + tid], smax[tid]);
}

// ---------------------------------------------------------------------------
__global__ void finalize_thr() {
    int i = blockIdx.x * blockDim.x + threadIdx.x;
    if (i < N_THR) {
        unsigned k = g_thr_keys[i];
        unsigned u = (k & 0x80000000u) ? (k & 0x7FFFFFFFu) : ~k;
        float thr  = __uint_as_float(u) + 1e-4f;
        g_thrv[i]  = make_float4(thr, 0.4f * thr, 8.0f / thr, INH * thr);
    }
}

// ---------------------------------------------------------------------------
// LIF + ASF + WTA + inhibition. Same transpose structure as R2 (proven
// bit-exact) but SOFTWARE-PIPELINED: t+1's global loads are issued right
// after the first barrier, overlapping DRAM latency with the whole
// compute/argmax/store phase of step t. Double-buffered smem tiles keep it
// WAR-safe at 2 barriers per timestep.
__global__ void __launch_bounds__(1024, 2) lif_kernel(float* __restrict__ out) {
    __shared__ float  smi[2][COUT][33];  // i tiles, [channel][pixel]
    __shared__ float  sms[2][COUT][33];  // spike tiles
    __shared__ float4 sthr[N_THR];       // cached thresholds

    const int tx  = threadIdx.x;         // lane
    const int ty  = threadIdx.y;         // warp
    const int tid = ty * 32 + tx;
    const int b   = blockIdx.x >> 7;     // 128 blocks per batch image
    const int spb = (blockIdx.x & 127) * 32;

    for (int i = tid; i < N_THR; i += 1024) sthr[i] = g_thrv[i];

    // global row addresses for the load/store (x = pixel) identity
    const int tstride = B_SZ * COUT * SPAT;            // elements per timestep
    const int row0    = (b * COUT + ty) * SPAT + spb + tx;
    const int row1    = row0 + 32 * SPAT;

    float l0 = g_i[row0];                // prefetch t = 0
    float l1 = g_i[row1];

    // compute-phase identity: pixel = ty, channels = tx, tx+32
    float mem0 = 0.f, mem1 = 0.f;

#pragma unroll
    for (int t = 0; t < T_STEPS; t++) {
        const int bt = t & 1;

        // ---- stage prefetched i values into transpose tile ----
        smi[bt][ty][tx]      = l0;
        smi[bt][ty + 32][tx] = l1;
        __syncthreads();

        // ---- prefetch t+1 (overlaps everything below) ----
        if (t + 1 < T_STEPS) {
            l0 = g_i[row0 + (t + 1) * tstride];
            l1 = g_i[row1 + (t + 1) * tstride];
        }

        // ---- compute phase: x = channel ----
        const float  i0  = smi[bt][tx][ty];
        const float  i1  = smi[bt][tx + 32][ty];
        const float4 tv0 = sthr[t * COUT + tx];
        const float4 tv1 = sthr[t * COUT + tx + 32];

        // ASF: thr * sigmoid((max(i,0) - 0.4*thr) * (8/thr))
        float z0 = (fmaxf(i0, 0.f) - tv0.y) * tv0.z;
        float z1 = (fmaxf(i1, 0.f) - tv1.y) * tv1.z;
        float asf0 = tv0.x / (1.f + expf(-z0));
        float asf1 = tv1.x / (1.f + expf(-z1));

        mem0 = fmaf(mem0, DECAY, asf0);
        mem1 = fmaf(mem1, DECAY, asf1);

        const int   s0i = mem0 > tv0.x ? 1 : 0;
        const int   s1i = mem1 > tv1.x ? 1 : 0;
        const float sc0 = s0i ? mem0 : 0.f;
        const float sc1 = s1i ? mem1 : 0.f;

        // per-lane candidate; lower channel wins ties (argmax-first semantics)
        float bs; int bi;
        if (sc0 >= sc1) { bs = sc0; bi = (tx << 1) | s0i; }
        else            { bs = sc1; bi = ((tx + 32) << 1) | s1i; }
#pragma unroll
        for (int m = 16; m >= 1; m >>= 1) {
            float os = __shfl_xor_sync(0xffffffffu, bs, m);
            int   oi = __shfl_xor_sync(0xffffffffu, bi, m);
            if (os > bs || (os == bs && (oi >> 1) < (bi >> 1))) { bs = os; bi = oi; }
        }
        const int   wc  = bi >> 1;
        const float any = (float)(bi & 1);            // winner's spike -> any_sp

        const float sn0 = (wc == tx)      ? (float)s0i : 0.f;
        const float sn1 = (wc == tx + 32) ? (float)s1i : 0.f;

        // reset fired winner; inhibit everyone else at spiking locations
        mem0 = (sn0 > 0.f) ? 0.f : fmaf(-tv0.w, any, mem0);
        mem1 = (sn1 > 0.f) ? 0.f : fmaf(-tv1.w, any, mem1);

        sms[bt][tx][ty]      = sn0;
        sms[bt][tx + 32][ty] = sn1;
        __syncthreads();

        // ---- store phase: x = pixel (coalesced) ----
        out[row0 + t * tstride] = sms[bt][ty][tx];
        out[row1 + t * tstride] = sms[bt][ty + 32][tx];
    }
}

// ---------------------------------------------------------------------------
extern "C" void kernel_launch(void* const* d_in, const int* in_sizes, int n_in,
                              void* d_out, int out_size) {
    const float* x = (const float*)d_in[0];
    const float* W = (const float*)d_in[1];
    if (n_in >= 2 && in_sizes[0] == COUT * CIN * 9) {  // defensive order swap
        const float* tmp = x; x = W; W = tmp;
    }

    init_keys<<<1, N_THR>>>();

    dim3 cb(32, 8);
    dim3 cg(2, 8, T_STEPS * B_SZ);
    conv_kernel<<<cg, cb>>>(x, W);

    finalize_thr<<<1, N_THR>>>();

    lif_kernel<<<(B_SZ * SPAT) / 32, dim3(32, 32)>>>((float*)d_out);
}

// round 5
// speedup vs baseline: 4.8979x; 1.2985x over previous
#include <cuda_runtime.h>

#define T_STEPS 10
#define B_SZ    32
#define CIN     3
#define COUT    64
#define SPAT    4096            // 64*64
#define N_THR   (T_STEPS * COUT)
#define DECAY   0.2f
#define INH     1.625f

// Scratch: conv results for all timesteps, layout (t,b,c,h,w).
__device__ float    g_i[T_STEPS * B_SZ * COUT * SPAT];   // 335.5 MB
__device__ unsigned g_thr_keys[N_THR];
__device__ float4   g_thrv[N_THR];                       // {thr, 0.4*thr, 8/thr, INH*thr}

// ---------------------------------------------------------------------------
__global__ void init_keys() {
    int i = blockIdx.x * blockDim.x + threadIdx.x;
    if (i < N_THR) g_thr_keys[i] = 0u;   // key 0 == very negative float
}

// ---------------------------------------------------------------------------
// Conv 3x3, stride 1, pad 1. Block = 128 threads; each thread computes a
// 4-tall column of pixels, so each weight fetch feeds 108 FMAs. Per-(t,c)
// max via warp REDUX -> per-warp smem slot -> block reduce -> global atomic
// (no same-address ATOMS serialization).
__global__ void __launch_bounds__(128) conv_kernel(const float* __restrict__ x,
                                                   const float* __restrict__ Wt) {
    __shared__ float    xs[CIN][18][34];     // 32x16 tile + halo
    __shared__ float    ws[COUT * 28];       // 27 weights + 1 pad per channel
    __shared__ unsigned swm[COUT][4];        // per-warp max keys

    const int tb  = blockIdx.z;              // t*B + b
    const int t   = tb >> 5;
    const int tid = threadIdx.y * 32 + threadIdx.x;
    const int wid = threadIdx.y;             // 4 warps

    for (int idx = tid; idx < COUT * 27; idx += 128) {
        int co = idx / 27;
        ws[co * 28 + (idx - co * 27)] = Wt[idx];
    }

    const float* xb = x + tb * (CIN * SPAT);
    const int y0 = blockIdx.y * 16;
    const int x0 = blockIdx.x * 32;
    for (int idx = tid; idx < CIN * 612; idx += 128) {
        int ci  = idx / 612;
        int rem = idx - ci * 612;
        int yy  = rem / 34;
        int xx  = rem - yy * 34;
        int gy = y0 + yy - 1, gx = x0 + xx - 1;
        float v = 0.f;
        if ((unsigned)gy < 64u && (unsigned)gx < 64u) v = xb[ci * SPAT + gy * 64 + gx];
        xs[ci][yy][xx] = v;
    }
    __syncthreads();

    const int px = threadIdx.x;
    const int py = threadIdx.y;              // 4 row-groups of 4
    // rows y0+4py .. y0+4py+3 ; need xs rows 4py .. 4py+5
    float r[CIN][6][3];
#pragma unroll
    for (int ci = 0; ci < CIN; ci++)
#pragma unroll
        for (int rr = 0; rr < 6; rr++)
#pragma unroll
            for (int kx = 0; kx < 3; kx++)
                r[ci][rr][kx] = xs[ci][4 * py + rr][px + kx];

    float* out = g_i + tb * (COUT * SPAT) + (y0 + 4 * py) * 64 + x0 + px;

#pragma unroll 1
    for (int co = 0; co < COUT; co++) {
        float wl[28];
        float4* wlv = (float4*)wl;
        const float4* wv = (const float4*)(ws + co * 28);
#pragma unroll
        for (int q = 0; q < 7; q++) wlv[q] = wv[q];

        float accs[4];
#pragma unroll
        for (int ry = 0; ry < 4; ry++) {
            float a0 = 0.f, a1 = 0.f, a2 = 0.f;
#pragma unroll
            for (int ky = 0; ky < 3; ky++)
#pragma unroll
                for (int kx = 0; kx < 3; kx++) {
                    const int j = ky * 3 + kx;
                    a0 = fmaf(r[0][ry + ky][kx], wl[j],      a0);
                    a1 = fmaf(r[1][ry + ky][kx], wl[j + 9],  a1);
                    a2 = fmaf(r[2][ry + ky][kx], wl[j + 18], a2);
                }
            accs[ry] = (a0 + a1) + a2;
            out[co * SPAT + ry * 64] = accs[ry];
        }

        float mx = fmaxf(fmaxf(accs[0], accs[1]), fmaxf(accs[2], accs[3]));
        unsigned u   = __float_as_uint(mx);
        unsigned key = ((int)u < 0) ? ~u : (u | 0x80000000u);   // order-preserving
        key = __reduce_max_sync(0xffffffffu, key);
        if (px == 0) swm[co][wid] = key;
    }
    __syncthreads();
    if (tid < COUT) {
        unsigned m = swm[tid][0];
        m = max(m, swm[tid][1]); m = max(m, swm[tid][2]); m = max(m, swm[tid][3]);
        atomicMax(&g_thr_keys[t * COUT + tid], m);
    }
}

// ---------------------------------------------------------------------------
__global__ void finalize_thr() {
    int i = blockIdx.x * blockDim.x + threadIdx.x;
    if (i < N_THR) {
        unsigned k = g_thr_keys[i];
        unsigned u = (k & 0x80000000u) ? (k & 0x7FFFFFFFu) : ~k;
        float thr  = __uint_as_float(u) + 1e-4f;
        g_thrv[i]  = make_float4(thr, 0.4f * thr, 8.0f / thr, INH * thr);
    }
}

// ---------------------------------------------------------------------------
// LIF + ASF + WTA + inhibition. Software-pipelined transpose kernel (R4) with:
//  * WTA argmax via 2 REDUX ops instead of a 5-deep shuffle butterfly
//  * spike transpose tile replaced by a single per-pixel winner code word
__global__ void __launch_bounds__(1024, 2) lif_kernel(float* __restrict__ out) {
    __shared__ float  smi[2][COUT][33];  // i tiles, [channel][pixel]
    __shared__ int    swz[2][32];        // winner code per pixel
    __shared__ float4 sthr[N_THR];       // cached thresholds

    const int tx  = threadIdx.x;         // lane
    const int ty  = threadIdx.y;         // warp
    const int tid = ty * 32 + tx;
    const int b   = blockIdx.x >> 7;     // 128 blocks per batch image
    const int spb = (blockIdx.x & 127) * 32;

    for (int i = tid; i < N_THR; i += 1024) sthr[i] = g_thrv[i];

    // global row addresses for the load/store (x = pixel) identity
    const int tstride = B_SZ * COUT * SPAT;            // elements per timestep
    const int row0    = (b * COUT + ty) * SPAT + spb + tx;
    const int row1    = row0 + 32 * SPAT;

    float l0 = g_i[row0];                // prefetch t = 0
    float l1 = g_i[row1];

    // compute-phase identity: pixel = ty, channels = tx, tx+32
    float mem0 = 0.f, mem1 = 0.f;

#pragma unroll
    for (int t = 0; t < T_STEPS; t++) {
        const int bt = t & 1;

        // ---- stage prefetched i values into transpose tile ----
        smi[bt][ty][tx]      = l0;
        smi[bt][ty + 32][tx] = l1;
        __syncthreads();

        // ---- prefetch t+1 (overlaps everything below) ----
        if (t + 1 < T_STEPS) {
            l0 = g_i[row0 + (t + 1) * tstride];
            l1 = g_i[row1 + (t + 1) * tstride];
        }

        // ---- compute phase: x = channel ----
        const float  i0  = smi[bt][tx][ty];
        const float  i1  = smi[bt][tx + 32][ty];
        const float4 tv0 = sthr[t * COUT + tx];
        const float4 tv1 = sthr[t * COUT + tx + 32];

        // ASF: thr * sigmoid((max(i,0) - 0.4*thr) * (8/thr))
        float z0 = (fmaxf(i0, 0.f) - tv0.y) * tv0.z;
        float z1 = (fmaxf(i1, 0.f) - tv1.y) * tv1.z;
        float asf0 = tv0.x / (1.f + expf(-z0));
        float asf1 = tv1.x / (1.f + expf(-z1));

        mem0 = fmaf(mem0, DECAY, asf0);
        mem1 = fmaf(mem1, DECAY, asf1);

        const int   s0i = mem0 > tv0.x ? 1 : 0;
        const int   s1i = mem1 > tv1.x ? 1 : 0;
        const float sc0 = s0i ? mem0 : 0.f;
        const float sc1 = s1i ? mem1 : 0.f;

        // per-lane candidate; lower channel wins ties (argmax-first semantics)
        float bs; int bi;
        if (sc0 >= sc1) { bs = sc0; bi = (tx << 1) | s0i; }
        else            { bs = sc1; bi = ((tx + 32) << 1) | s1i; }

        // warp argmax: REDUX max on order-preserving key, REDUX min on
        // (chan<<1)|spike among tied lanes -> first-index tiebreak
        unsigned ub  = __float_as_uint(bs);
        unsigned key = ((int)ub < 0) ? ~ub : (ub | 0x80000000u);
        unsigned mk  = __reduce_max_sync(0xffffffffu, key);
        unsigned cand = (key == mk) ? (unsigned)bi : 0x7fffffffu;
        const int wz = (int)__reduce_min_sync(0xffffffffu, cand);

        const int   wc  = wz >> 1;
        const float any = (float)(wz & 1);            // winner's spike -> any_sp

        const float sn0 = (wc == tx)      ? (float)s0i : 0.f;
        const float sn1 = (wc == tx + 32) ? (float)s1i : 0.f;

        // reset fired winner; inhibit everyone else at spiking locations
        mem0 = (sn0 > 0.f) ? 0.f : fmaf(-tv0.w, any, mem0);
        mem1 = (sn1 > 0.f) ? 0.f : fmaf(-tv1.w, any, mem1);

        if (tx == 0) swz[bt][ty] = wz;   // one word per pixel
        __syncthreads();

        // ---- store phase: x = pixel (coalesced); reconstruct spikes ----
        const int wzp = swz[bt][tx];
        out[row0 + t * tstride] = (wzp == ((ty << 1) | 1))        ? 1.f : 0.f;
        out[row1 + t * tstride] = (wzp == (((ty + 32) << 1) | 1)) ? 1.f : 0.f;
    }
}

// ---------------------------------------------------------------------------
extern "C" void kernel_launch(void* const* d_in, const int* in_sizes, int n_in,
                              void* d_out, int out_size) {
    const float* x = (const float*)d_in[0];
    const float* W = (const float*)d_in[1];
    if (n_in >= 2 && in_sizes[0] == COUT * CIN * 9) {  // defensive order swap
        const float* tmp = x; x = W; W = tmp;
    }

    init_keys<<<1, N_THR>>>();

    dim3 cb(32, 4);
    dim3 cg(2, 4, T_STEPS * B_SZ);
    conv_kernel<<<cg, cb>>>(x, W);

    finalize_thr<<<1, N_THR>>>();

    lif_kernel<<<(B_SZ * SPAT) / 32, dim3(32, 32)>>>((float*)d_out);
}